// round 1
// baseline (speedup 1.0000x reference)
#include <cuda_runtime.h>

// x: (16, 256, 128, 128) fp32.
// out[b,c,h,w] = 0.5 * (x[b,c,2*(h/2),2*(w/2)] + x[b,c,2*(h/2)+1,2*(w/2)]
//                     + x[b,c,2*(h/2),2*(w/2)+1] + x[b,c,2*(h/2)+1,2*(w/2)+1])
//
// Layout: treat tensor as ROWPAIRS = 16*256*64 row pairs, each row = 128 floats
// = 32 float4. Each thread handles one row pair x one float4 (4 w-elements =
// 2 column pairs): 2 x LDG.128 in, 2 x STG.128 out.

__global__ void __launch_bounds__(256) wfdm_kernel(
    const float4* __restrict__ in, float4* __restrict__ out, int total)
{
    int tid = blockIdx.x * blockDim.x + threadIdx.x;
    if (tid >= total) return;

    int col     = tid & 31;        // float4 index within row (0..31)
    int rowpair = tid >> 5;        // which pair of rows

    // row stride = 32 float4; a row pair spans 64 float4
    int idx0 = rowpair * 64 + col;   // top row
    int idx1 = idx0 + 32;            // bottom row

    float4 t = in[idx0];
    float4 b = in[idx1];

    float s0 = (t.x + t.y + b.x + b.y) * 0.5f;
    float s1 = (t.z + t.w + b.z + b.w) * 0.5f;

    float4 o = make_float4(s0, s0, s1, s1);
    out[idx0] = o;
    out[idx1] = o;
}

extern "C" void kernel_launch(void* const* d_in, const int* in_sizes, int n_in,
                              void* d_out, int out_size)
{
    const float4* in = (const float4*)d_in[0];
    float4* out = (float4*)d_out;

    // total threads = elements / 8 (each thread covers 8 floats: 2 x float4)
    int total = out_size / 8;  // 16*256*128*128 / 8 = 8,388,608
    int threads = 256;
    int blocks = (total + threads - 1) / threads;
    wfdm_kernel<<<blocks, threads>>>(in, out, total);
}